// round 14
// baseline (speedup 1.0000x reference)
#include <cuda_runtime.h>
#include <math.h>

#define BATCH 256
#define TLEN  50
#define NOBS  8192
#define NKC   50
#define NBLK  128
#define NTHR  512
#define F4_TOT     (NOBS * NKC / 4)     // 102400 float4s of A
#define F4_PER_BLK (F4_TOT / NBLK)      // 800 per block

// ---- device-global scratch (no allocations allowed) ----
__device__ unsigned char      g_assign[NOBS];
__device__ float              g_probs_scratch[BATCH * TLEN];
__device__ unsigned long long g_bar;     // monotone epoch barrier

__device__ __forceinline__ float sigm(float x) {
    return 1.0f / (1.0f + __expf(-x));
}

// ============================================================
// Single fused kernel: 128 blocks x 512 threads (one wave),
// two batch rows per block.
//  PRE-BARRIER (independent of other blocks):
//   - A-slice scan -> g_assign bytes (this block's 1/128)
//   - 200 finder threads per half argmax-scan A rows pk_t/ck_t
//     directly -> s_ap/s_ack  (no dependence on g_assign!)
//   - sigmoids -> per-step Moebius tables -> parallel compose
//     -> probs written, compact state in shared
//   - barrier ARRIVE right after the slice is published; WAIT
//     only after compose (hidden behind compute)
//  POST-BARRIER: expansion only (needs full g_assign).
// ============================================================
__global__ __launch_bounds__(NTHR, 1)
void bkt_one(const float* __restrict__ A,
             const int*   __restrict__ prev_kc,
             const int*   __restrict__ curr_kc,
             const float* __restrict__ prev_corr,
             const float* __restrict__ kc_logits,
             float*       __restrict__ probs_out,
             float*       __restrict__ state_out,
             int do_state) {
    __shared__ unsigned char s_assign[NOBS];     // 8 KB (expansion only)
    __shared__ float4        s_pr[NKC];
    __shared__ float         s_p4[NKC];
    __shared__ float4        s_M[2][TLEN];
    __shared__ float2        s_ozw[2][TLEN];
    __shared__ float         s_state[2][NKC];
    __shared__ unsigned char s_ap[2][TLEN];
    __shared__ unsigned char s_ack[2][TLEN];

    const int tid = threadIdx.x;
    const int r   = tid >> 8;          // row half
    const int rt  = tid & 255;
    const int b   = blockIdx.x * 2 + r;

    // ---- finder index loads first (head of the 2-hop chain) ----
    // 200 finder threads per half: q = rt>>1 in [0,99];
    // q < 50 -> prev_kc[q], q >= 50 -> curr_kc[q-50]; h picks row half.
    int q = -1, h = 0, idxv = 0;
    if (rt < 4 * TLEN) {
        q = rt >> 1;  h = rt & 1;
        idxv = (q < TLEN) ? prev_kc[b * TLEN + q]
                          : curr_kc[b * TLEN + (q - TLEN)];
    }
    float cr = 0.0f;
    if (rt < TLEN) cr = prev_corr[b * TLEN + rt];

    // ---- A-slice scan -> g_assign (independent, fills latency) ----
    {
        const float4* A4 = (const float4*)A;
        for (int i = tid; i < F4_PER_BLK; i += NTHR) {
            int gi = blockIdx.x * F4_PER_BLK + i;
            float4 v = A4[gi];
            int base = gi * 4;
            if (v.x > 0.5f) { int f = base + 0; g_assign[f / NKC] = (unsigned char)(f % NKC); }
            if (v.y > 0.5f) { int f = base + 1; g_assign[f / NKC] = (unsigned char)(f % NKC); }
            if (v.z > 0.5f) { int f = base + 2; g_assign[f / NKC] = (unsigned char)(f % NKC); }
            if (v.w > 0.5f) { int f = base + 3; g_assign[f / NKC] = (unsigned char)(f % NKC); }
        }
    }

    // ---- sigmoids (once per block) ----
    if (tid < NKC) {
        float4 p;
        p.x = sigm(kc_logits[tid * 5 + 0]);
        p.y = sigm(kc_logits[tid * 5 + 1]);
        p.z = sigm(kc_logits[tid * 5 + 2]);
        p.w = sigm(kc_logits[tid * 5 + 3]);
        s_pr[tid] = p;
        s_p4[tid] = sigm(kc_logits[tid * 5 + 4]);
    }

    // ---- argmax finders: scan A row idxv (exactly one 1.0) ----
    if (q >= 0) {
        const float2* A2 = (const float2*)A;   // rows are 8B-aligned (200 B)
        const float2* row = A2 + (size_t)idxv * (NKC / 2);
        int j0 = h ? 13 : 0;
        int j1 = h ? 25 : 13;
        int kk = -1;
        #pragma unroll
        for (int j = j0; j < j1; j++) {
            float2 v = row[j];
            if (v.x > 0.5f) kk = j * 2;
            if (v.y > 0.5f) kk = j * 2 + 1;
        }
        if (kk >= 0) {
            if (q < TLEN) s_ap[r][q]          = (unsigned char)kk;
            else          s_ack[r][q - TLEN]  = (unsigned char)kk;
        }
    }

    // ---- publish slice, EARLY barrier arrive ----
    if (do_state) __threadfence();
    __syncthreads();                       // finder/sigmoid STS + slice STGs done
    unsigned long long tgt = 0;
    if (do_state && tid == 0) {
        unsigned long long old = atomicAdd(&g_bar, 1ULL);
        tgt = (old / (unsigned long long)NBLK + 1ULL) * (unsigned long long)NBLK;
    }

    // ---- per-step Moebius tables ----
    if (rt < TLEN) {
        int ap = (int)s_ap[r][rt];
        int ac = (int)s_ack[r][rt];
        float4 pp = s_pr[ap];
        float o0, o1;
        if (cr > 0.5f) { o0 = pp.z;        o1 = pp.w;        }
        else           { o0 = 1.0f - pp.z; o1 = 1.0f - pp.w; }
        float d10 = o1 - o0;
        float c1  = 1.0f - pp.y - pp.x;
        // pred = (A*s + B) / (C*s + D)
        s_M[r][rt] = make_float4(fmaf(pp.x, d10, c1 * o1), pp.x * o0, d10, o0);
        float4 qq = s_pr[ac];
        s_ozw[r][rt] = make_float2(qq.w - qq.z, qq.z);
    }
    __syncthreads();

    // ---- parallel Moebius composition (r9-validated) ----
    if (rt < TLEN) {
        // pass A: out[t], t = rt (t=0 -> identity)
        const int t = rt;
        const int k = (int)s_ack[r][t];
        float a = 1.0f, bm = 0.0f, c = 0.0f, d = 1.0f;
        #pragma unroll 7
        for (int i = 1; i < TLEN; i++) {
            float4 M = s_M[r][i];
            bool take = (i <= t) && ((int)s_ap[r][i] == k);
            float Mx = take ? M.x : 1.0f;
            float My = take ? M.y : 0.0f;
            float Mz = take ? M.z : 0.0f;
            float Mw = take ? M.w : 1.0f;
            float na = fmaf(Mx, a,  My * c);
            float nb = fmaf(Mx, bm, My * d);
            float nc = fmaf(Mz, a,  Mw * c);
            float nd = fmaf(Mz, bm, Mw * d);
            a = na; bm = nb; c = nc; d = nd;
        }
        float s0 = s_p4[k];
        float sf = __fdividef(fmaf(a, s0, bm), fmaf(c, s0, d));
        float2 zw = s_ozw[r][t];
        probs_out[b * TLEN + t] = fmaf(zw.x, sf, zw.y);
    } else if (rt >= 64 && rt < 64 + NKC) {
        // pass B: final state[k], k = rt-64
        const int k = rt - 64;
        float a = 1.0f, bm = 0.0f, c = 0.0f, d = 1.0f;
        #pragma unroll 7
        for (int i = 1; i < TLEN; i++) {
            float4 M = s_M[r][i];
            bool take = ((int)s_ap[r][i] == k);
            float Mx = take ? M.x : 1.0f;
            float My = take ? M.y : 0.0f;
            float Mz = take ? M.z : 0.0f;
            float Mw = take ? M.w : 1.0f;
            float na = fmaf(Mx, a,  My * c);
            float nb = fmaf(Mx, bm, My * d);
            float nc = fmaf(Mz, a,  Mw * c);
            float nd = fmaf(Mz, bm, Mw * d);
            a = na; bm = nb; c = nc; d = nd;
        }
        float s0 = s_p4[k];
        s_state[r][k] = __fdividef(fmaf(a, s0, bm), fmaf(c, s0, d));
    }
    __syncthreads();   // s_state complete

    if (!do_state) return;

    // ---- LATE barrier wait (mostly already released) ----
    if (tid == 0) {
        volatile unsigned long long* pc = &g_bar;
        while (*pc < tgt) { __nanosleep(32); }
        __threadfence();   // acquire
    }
    __syncthreads();

    // ---- expansion: copy full g_assign -> shared, gather, store ----
    {
        const int4* src = (const int4*)g_assign;
        ((int4*)s_assign)[tid] = src[tid];     // 512 x 16B = 8 KB
    }
    __syncthreads();

    {
        float4*       o  = (float4*)(state_out + (size_t)b * NOBS);
        const uchar4* a4 = (const uchar4*)s_assign;
        const float*  st = s_state[r];
        #pragma unroll
        for (int j = 0; j < 8; j++) {
            uchar4 a = a4[rt + 256 * j];
            o[rt + 256 * j] = make_float4(st[a.x], st[a.y], st[a.z], st[a.w]);
        }
    }
}

// ============================================================
extern "C" void kernel_launch(void* const* d_in, const int* in_sizes, int n_in,
                              void* d_out, int out_size) {
    const int*   prev_kc   = (const int*)  d_in[0];
    const int*   curr_kc   = (const int*)  d_in[1];
    const float* prev_corr = (const float*)d_in[2];
    const float* kc_logits = (const float*)d_in[3];
    const float* A         = (const float*)d_in[4];
    float*       out       = (float*)d_out;

    // Output layout: [probs (256*50) | state (256*8192)] concatenated.
    float* probs_out = out;
    float* state_out = out + BATCH * TLEN;
    int    do_state  = 1;

    if (out_size == BATCH * TLEN) {
        do_state  = 0;
        state_out = out;                 // unused
    } else if (out_size == BATCH * NOBS) {
        void* scratch = nullptr;
        cudaGetSymbolAddress(&scratch, g_probs_scratch);
        probs_out = (float*)scratch;
        state_out = out;
    }

    bkt_one<<<NBLK, NTHR>>>(A, prev_kc, curr_kc, prev_corr, kc_logits,
                            probs_out, state_out, do_state);
}

// round 15
// speedup vs baseline: 1.1805x; 1.1805x over previous
#include <cuda_runtime.h>
#include <math.h>

#define BATCH 256
#define TLEN  50
#define NOBS  8192
#define NKC   50
#define F4_TOT     (NOBS * NKC / 4)     // 102400 float4s of A
#define F4_PER_BLK (F4_TOT / 128)       // 800 per block

// ---- device-global scratch (no allocations allowed) ----
__device__ unsigned char g_assign[NOBS];          // assign[] as uint8
__device__ unsigned char g_apk[BATCH * TLEN];     // assign[pk] | corr<<7
__device__ unsigned char g_ack[BATCH * TLEN];     // assign[ck]
__device__ float         g_probs_scratch[BATCH * TLEN];

__device__ __forceinline__ float sigm(float x) {
    return 1.0f / (1.0f + __expf(-x));
}

// ============================================================
// k1: 128 blocks x 512 threads (single wave), 2 batch rows/block.
//  - A-slice scan -> g_assign (this block's 1/128 of A)
//  - finder threads resolve assign[pk_t]/assign[ck_t] by scanning
//    the one-hot rows of A DIRECTLY (no dependence on g_assign),
//    fold the corr bit, and write coalesced u8 tables g_apk/g_ack.
// This removes the entire index-resolution chain from k2's head.
// ============================================================
__global__ __launch_bounds__(512)
void k1_prep(const float* __restrict__ A,
             const int*   __restrict__ prev_kc,
             const int*   __restrict__ curr_kc,
             const float* __restrict__ prev_corr) {
    __shared__ unsigned char s_ap[2][TLEN];
    __shared__ unsigned char s_ack[2][TLEN];

    const int tid = threadIdx.x;
    const int r   = tid >> 8;
    const int rt  = tid & 255;
    const int b   = blockIdx.x * 2 + r;

    // ---- finder index loads (head of chain, issued first) ----
    int q = -1, h = 0, idxv = 0;
    if (rt < 4 * TLEN) {                  // 200 finder threads per half
        q = rt >> 1;  h = rt & 1;
        idxv = (q < TLEN) ? prev_kc[b * TLEN + q]
                          : curr_kc[b * TLEN + (q - TLEN)];
    }
    float cr = 0.0f;
    if (rt < TLEN) cr = prev_corr[b * TLEN + rt];

    // ---- A-slice scan -> g_assign (independent, fills latency) ----
    {
        const float4* A4 = (const float4*)A;
        #pragma unroll
        for (int i = 0; i < F4_PER_BLK / 512; i++) {   // 800/512 -> loop+tail
            int li = tid + 512 * i;
            int gi = blockIdx.x * F4_PER_BLK + li;
            float4 v = A4[gi];
            int base = gi * 4;
            if (v.x > 0.5f) { int f = base + 0; g_assign[f / NKC] = (unsigned char)(f % NKC); }
            if (v.y > 0.5f) { int f = base + 1; g_assign[f / NKC] = (unsigned char)(f % NKC); }
            if (v.z > 0.5f) { int f = base + 2; g_assign[f / NKC] = (unsigned char)(f % NKC); }
            if (v.w > 0.5f) { int f = base + 3; g_assign[f / NKC] = (unsigned char)(f % NKC); }
        }
        int li = tid + 512 * (F4_PER_BLK / 512);
        if (li < F4_PER_BLK) {
            int gi = blockIdx.x * F4_PER_BLK + li;
            float4 v = A4[gi];
            int base = gi * 4;
            if (v.x > 0.5f) { int f = base + 0; g_assign[f / NKC] = (unsigned char)(f % NKC); }
            if (v.y > 0.5f) { int f = base + 1; g_assign[f / NKC] = (unsigned char)(f % NKC); }
            if (v.z > 0.5f) { int f = base + 2; g_assign[f / NKC] = (unsigned char)(f % NKC); }
            if (v.w > 0.5f) { int f = base + 3; g_assign[f / NKC] = (unsigned char)(f % NKC); }
        }
    }

    // ---- finders: scan one-hot row A[idxv,:] (exactly one 1.0) ----
    if (q >= 0) {
        const float2* row = (const float2*)A + (size_t)idxv * (NKC / 2);
        int j0 = h ? 13 : 0;
        int j1 = h ? 25 : 13;
        int kk = -1;
        #pragma unroll
        for (int j = j0; j < j1; j++) {
            float2 v = row[j];
            if (v.x > 0.5f) kk = j * 2;
            if (v.y > 0.5f) kk = j * 2 + 1;
        }
        if (kk >= 0) {
            if (q < TLEN) s_ap[r][q]         = (unsigned char)kk;
            else          s_ack[r][q - TLEN] = (unsigned char)kk;
        }
    }
    __syncthreads();

    // ---- write resolved tables (coalesced u8) ----
    if (rt < TLEN) {
        g_apk[b * TLEN + rt] = s_ap[r][rt] |
                               (cr > 0.5f ? (unsigned char)0x80 : (unsigned char)0);
        g_ack[b * TLEN + rt] = s_ack[r][rt];
    }
}

// ============================================================
// k2: 128 blocks x 512 threads (single wave), 2 rows/block.
// Head chain is now just one coalesced L2-hot byte load of the
// pre-resolved tables. Then: Moebius tables -> parallel compose
// (r9-validated) -> expansion.
// ============================================================
__global__ __launch_bounds__(512)
void k2_fused(const float* __restrict__ kc_logits,
              float*       __restrict__ probs_out,
              float*       __restrict__ state_out,
              int do_state) {
    __shared__ unsigned char s_assign[NOBS];     // 8 KB (expansion only)
    __shared__ float4        s_pr[NKC];
    __shared__ float         s_p4[NKC];
    __shared__ float4        s_M[2][TLEN];
    __shared__ float2        s_ozw[2][TLEN];
    __shared__ float         s_state[2][NKC];
    __shared__ unsigned char s_ap[2][TLEN];
    __shared__ unsigned char s_ack[2][TLEN];

    const int tid = threadIdx.x;
    const int r   = tid >> 8;
    const int rt  = tid & 255;
    const int b   = blockIdx.x * 2 + r;

    // ---- head: pre-resolved tables (coalesced, L2-hot) ----
    unsigned int af = 0; int ac = 0;
    if (rt < TLEN) {
        af = g_apk[b * TLEN + rt];
        ac = g_ack[b * TLEN + rt];
        s_ap[r][rt]  = (unsigned char)(af & 0x7fu);
        s_ack[r][rt] = (unsigned char)ac;
    }

    // ---- s_assign copy (expansion only; overlaps) ----
    {
        const int4* src = (const int4*)g_assign;
        ((int4*)s_assign)[tid] = src[tid];
    }

    // ---- sigmoids (once per block) ----
    if (tid < NKC) {
        float4 p;
        p.x = sigm(kc_logits[tid * 5 + 0]);
        p.y = sigm(kc_logits[tid * 5 + 1]);
        p.z = sigm(kc_logits[tid * 5 + 2]);
        p.w = sigm(kc_logits[tid * 5 + 3]);
        s_pr[tid] = p;
        s_p4[tid] = sigm(kc_logits[tid * 5 + 4]);
    }
    __syncthreads();

    // ---- per-step Moebius tables ----
    if (rt < TLEN) {
        int ap = (int)(af & 0x7fu);
        float4 pp = s_pr[ap];
        float o0, o1;
        if (af & 0x80u) { o0 = pp.z;        o1 = pp.w;        }
        else            { o0 = 1.0f - pp.z; o1 = 1.0f - pp.w; }
        float d10 = o1 - o0;
        float c1  = 1.0f - pp.y - pp.x;
        // pred = (A*s + B) / (C*s + D)
        s_M[r][rt] = make_float4(fmaf(pp.x, d10, c1 * o1), pp.x * o0, d10, o0);
        float4 qq = s_pr[ac];
        s_ozw[r][rt] = make_float2(qq.w - qq.z, qq.z);
    }
    __syncthreads();

    // ---- parallel Moebius composition ----
    if (rt < TLEN) {
        // pass A: out[t], t = rt (t=0 -> identity)
        const int t = rt;
        const int k = (int)s_ack[r][t];
        float a = 1.0f, bm = 0.0f, c = 0.0f, d = 1.0f;
        #pragma unroll 7
        for (int i = 1; i < TLEN; i++) {
            float4 M = s_M[r][i];
            bool take = (i <= t) && ((int)s_ap[r][i] == k);
            float Mx = take ? M.x : 1.0f;
            float My = take ? M.y : 0.0f;
            float Mz = take ? M.z : 0.0f;
            float Mw = take ? M.w : 1.0f;
            float na = fmaf(Mx, a,  My * c);
            float nb = fmaf(Mx, bm, My * d);
            float nc = fmaf(Mz, a,  Mw * c);
            float nd = fmaf(Mz, bm, Mw * d);
            a = na; bm = nb; c = nc; d = nd;
        }
        float s0 = s_p4[k];
        float sf = __fdividef(fmaf(a, s0, bm), fmaf(c, s0, d));
        float2 zw = s_ozw[r][t];
        probs_out[b * TLEN + t] = fmaf(zw.x, sf, zw.y);
    } else if (rt >= 64 && rt < 64 + NKC) {
        // pass B: final state[k], k = rt-64
        const int k = rt - 64;
        float a = 1.0f, bm = 0.0f, c = 0.0f, d = 1.0f;
        #pragma unroll 7
        for (int i = 1; i < TLEN; i++) {
            float4 M = s_M[r][i];
            bool take = ((int)s_ap[r][i] == k);
            float Mx = take ? M.x : 1.0f;
            float My = take ? M.y : 0.0f;
            float Mz = take ? M.z : 0.0f;
            float Mw = take ? M.w : 1.0f;
            float na = fmaf(Mx, a,  My * c);
            float nb = fmaf(Mx, bm, My * d);
            float nc = fmaf(Mz, a,  Mw * c);
            float nd = fmaf(Mz, bm, Mw * d);
            a = na; bm = nb; c = nc; d = nd;
        }
        float s0 = s_p4[k];
        s_state[r][k] = __fdividef(fmaf(a, s0, bm), fmaf(c, s0, d));
    }
    __syncthreads();

    // ---- expansion: 8 uchar4 LDS gathers + 8 float4 stores/thread ----
    if (do_state) {
        float4*       o  = (float4*)(state_out + (size_t)b * NOBS);
        const uchar4* a4 = (const uchar4*)s_assign;
        const float*  st = s_state[r];
        #pragma unroll
        for (int j = 0; j < 8; j++) {
            uchar4 a = a4[rt + 256 * j];
            o[rt + 256 * j] = make_float4(st[a.x], st[a.y], st[a.z], st[a.w]);
        }
    }
}

// ============================================================
extern "C" void kernel_launch(void* const* d_in, const int* in_sizes, int n_in,
                              void* d_out, int out_size) {
    const int*   prev_kc   = (const int*)  d_in[0];
    const int*   curr_kc   = (const int*)  d_in[1];
    const float* prev_corr = (const float*)d_in[2];
    const float* kc_logits = (const float*)d_in[3];
    const float* A         = (const float*)d_in[4];
    float*       out       = (float*)d_out;

    k1_prep<<<128, 512>>>(A, prev_kc, curr_kc, prev_corr);

    // Output layout: [probs (256*50) | state (256*8192)] concatenated.
    float* probs_out = out;
    float* state_out = out + BATCH * TLEN;
    int    do_state  = 1;

    if (out_size == BATCH * TLEN) {
        do_state  = 0;
        state_out = out;                 // unused
    } else if (out_size == BATCH * NOBS) {
        void* scratch = nullptr;
        cudaGetSymbolAddress(&scratch, g_probs_scratch);
        probs_out = (float*)scratch;
        state_out = out;
    }

    k2_fused<<<BATCH / 2, 512>>>(kc_logits, probs_out, state_out, do_state);
}

// round 16
// speedup vs baseline: 1.3732x; 1.1633x over previous
#include <cuda_runtime.h>
#include <math.h>

#define BATCH 256
#define TLEN  50
#define NOBS  8192
#define NKC   50
#define REP   16      // state replication factor (bank-conflict mitigation)

// ---- device-global scratch (no allocations allowed) ----
__device__ unsigned char g_assign[NOBS];                 // assign[] as uint8
__device__ float         g_probs_scratch[BATCH * TLEN];  // fallback sink

__device__ __forceinline__ float sigm(float x) {
    return 1.0f / (1.0f + __expf(-x));
}

// ============================================================
// k1 (r12 form): recover assign[] from one-hot A. 100 blocks x
// 256 threads (single wave), 4 independent float4 loads/thread.
// ============================================================
__global__ __launch_bounds__(256)
void k1_prep(const float4* __restrict__ A4) {
    const int stride = 100 * 256;                 // 25600 threads
    int t = blockIdx.x * 256 + threadIdx.x;
    #pragma unroll
    for (int j = 0; j < 4; j++) {
        int idx = t + stride * j;                 // < 102400
        float4 v = A4[idx];
        int base = idx * 4;
        if (v.x > 0.5f) { int i = base + 0; g_assign[i / NKC] = (unsigned char)(i % NKC); }
        if (v.y > 0.5f) { int i = base + 1; g_assign[i / NKC] = (unsigned char)(i % NKC); }
        if (v.z > 0.5f) { int i = base + 2; g_assign[i / NKC] = (unsigned char)(i % NKC); }
        if (v.w > 0.5f) { int i = base + 3; g_assign[i / NKC] = (unsigned char)(i % NKC); }
    }
}

// ============================================================
// k2: 128 blocks x 512 threads (single wave), 2 rows/block.
//  - direct L2 gathers of assign[pk]/assign[ck] (r12-validated)
//  - compose by applying Moebius maps to the VECTOR (u,v)
//    sequentially: 4 FMA + 2 SEL per step (half the old cost)
//  - expansion reads state from a x16-REPLICATED shared table
//    (worst-case bank conflict 2 instead of ~4)
// ============================================================
__global__ __launch_bounds__(512)
void k2_fused(const int*   __restrict__ prev_kc,
              const int*   __restrict__ curr_kc,
              const float* __restrict__ prev_corr,
              const float* __restrict__ kc_logits,
              float*       __restrict__ probs_out,
              float*       __restrict__ state_out,
              int do_state) {
    __shared__ unsigned char s_assign[NOBS];       // 8 KB (expansion only)
    __shared__ float4        s_pr[NKC];
    __shared__ float         s_p4[NKC];
    __shared__ float4        s_M[2][TLEN];
    __shared__ float2        s_ozw[2][TLEN];
    __shared__ float         s_rep[2][NKC * REP];  // replicated final state
    __shared__ unsigned char s_ap[2][TLEN];
    __shared__ unsigned char s_ack[2][TLEN];

    const int tid = threadIdx.x;
    const int r   = tid >> 8;          // row half
    const int rt  = tid & 255;
    const int b   = blockIdx.x * 2 + r;

    // ---- issue scalar row loads first ----
    int   pkv = 0, ckv = 0;
    float cr  = 0.0f;
    if (rt < TLEN) {
        pkv = prev_kc[b * TLEN + rt];
        ckv = curr_kc[b * TLEN + rt];
        cr  = prev_corr[b * TLEN + rt];
    }

    // ---- s_assign copy (one int4/thread = 8 KB; overlaps) ----
    {
        const int4* src = (const int4*)g_assign;
        ((int4*)s_assign)[tid] = src[tid];
    }

    // ---- sigmoids (once per block) ----
    if (tid < NKC) {
        float4 p;
        p.x = sigm(kc_logits[tid * 5 + 0]);
        p.y = sigm(kc_logits[tid * 5 + 1]);
        p.z = sigm(kc_logits[tid * 5 + 2]);
        p.w = sigm(kc_logits[tid * 5 + 3]);
        s_pr[tid] = p;
        s_p4[tid] = sigm(kc_logits[tid * 5 + 4]);
    }

    // ---- direct L2 gathers (concurrent with copy) ----
    int ap = 0, ac = 0;
    if (rt < TLEN) {
        ap = g_assign[pkv];
        ac = g_assign[ckv];
        s_ap[r][rt]  = (unsigned char)ap;
        s_ack[r][rt] = (unsigned char)ac;
    }
    __syncthreads();

    // ---- per-step Moebius tables ----
    if (rt < TLEN) {
        float4 pp = s_pr[ap];
        float o0, o1;
        if (cr > 0.5f) { o0 = pp.z;        o1 = pp.w;        }
        else           { o0 = 1.0f - pp.z; o1 = 1.0f - pp.w; }
        float d10 = o1 - o0;
        float c1  = 1.0f - pp.y - pp.x;
        // pred = (A*s + B) / (C*s + D)
        s_M[r][rt] = make_float4(fmaf(pp.x, d10, c1 * o1), pp.x * o0, d10, o0);
        float4 q = s_pr[ac];
        s_ozw[r][rt] = make_float2(q.w - q.z, q.z);
    }
    __syncthreads();

    // ---- parallel composition: apply maps to the VECTOR (u,v) ----
    if (rt < TLEN) {
        // pass A: out[t], t = rt (t=0 -> no steps taken)
        const int t = rt;
        const int k = (int)s_ack[r][t];
        float u = s_p4[k], v = 1.0f;
        #pragma unroll 7
        for (int i = 1; i < TLEN; i++) {
            float4 M = s_M[r][i];                        // broadcast LDS
            bool take = (i <= t) && ((int)s_ap[r][i] == k);
            float nu = fmaf(M.x, u, M.y * v);
            float nv = fmaf(M.z, u, M.w * v);
            u = take ? nu : u;
            v = take ? nv : v;
        }
        float sf = __fdividef(u, v);
        float2 zw = s_ozw[r][t];
        probs_out[b * TLEN + t] = fmaf(zw.x, sf, zw.y);
    } else if (rt >= 64 && rt < 64 + NKC) {
        // pass B: final state[k], k = rt-64 -> replicated table
        const int k = rt - 64;
        float u = s_p4[k], v = 1.0f;
        #pragma unroll 7
        for (int i = 1; i < TLEN; i++) {
            float4 M = s_M[r][i];
            bool take = ((int)s_ap[r][i] == k);
            float nu = fmaf(M.x, u, M.y * v);
            float nv = fmaf(M.z, u, M.w * v);
            u = take ? nu : u;
            v = take ? nv : v;
        }
        float val = __fdividef(u, v);
        #pragma unroll
        for (int m = 0; m < REP; m++) s_rep[r][k * REP + m] = val;
    }
    __syncthreads();

    // ---- expansion: replicated-table gathers + float4 stores ----
    if (do_state) {
        float4*       o   = (float4*)(state_out + (size_t)b * NOBS);
        const uchar4* a4  = (const uchar4*)s_assign;
        const float*  st  = s_rep[r];
        const int     ofs = tid & (REP - 1);     // lane-spread replica pick
        #pragma unroll
        for (int j = 0; j < 8; j++) {
            uchar4 a = a4[rt + 256 * j];
            o[rt + 256 * j] = make_float4(st[a.x * REP + ofs],
                                          st[a.y * REP + ofs],
                                          st[a.z * REP + ofs],
                                          st[a.w * REP + ofs]);
        }
    }
}

// ============================================================
extern "C" void kernel_launch(void* const* d_in, const int* in_sizes, int n_in,
                              void* d_out, int out_size) {
    const int*    prev_kc   = (const int*)   d_in[0];
    const int*    curr_kc   = (const int*)   d_in[1];
    const float*  prev_corr = (const float*) d_in[2];
    const float*  kc_logits = (const float*) d_in[3];
    const float4* A4        = (const float4*)d_in[4];
    float*        out       = (float*)d_out;

    k1_prep<<<100, 256>>>(A4);

    // Output layout: [probs (256*50) | state (256*8192)] concatenated.
    float* probs_out = out;
    float* state_out = out + BATCH * TLEN;
    int    do_state  = 1;

    if (out_size == BATCH * TLEN) {
        do_state  = 0;
        state_out = out;                 // unused
    } else if (out_size == BATCH * NOBS) {
        void* scratch = nullptr;
        cudaGetSymbolAddress(&scratch, g_probs_scratch);
        probs_out = (float*)scratch;
        state_out = out;
    }

    k2_fused<<<BATCH / 2, 512>>>(prev_kc, curr_kc, prev_corr, kc_logits,
                                 probs_out, state_out, do_state);
}